// round 4
// baseline (speedup 1.0000x reference)
#include <cuda_runtime.h>
#include <cstdint>

#define L 1024
#define D 64
#define NBH 64
#define OUT_ELEMS (NBH*L*D)

__device__ float g_inv_l[NBH * L];   // per-row 1/sum(exp(s)), qk -> pv

__device__ __forceinline__ uint32_t f2tf(float x) {
    uint32_t r; asm("cvt.rna.tf32.f32 %0, %1;" : "=r"(r) : "f"(x)); return r;
}

__device__ __forceinline__ void mma_tf32(float* c,
    uint32_t a0, uint32_t a1, uint32_t a2, uint32_t a3, uint32_t b0, uint32_t b1)
{
    asm("mma.sync.aligned.m16n8k8.row.col.f32.tf32.tf32.f32 "
        "{%0,%1,%2,%3}, {%4,%5,%6,%7}, {%8,%9}, {%0,%1,%2,%3};"
        : "+f"(c[0]), "+f"(c[1]), "+f"(c[2]), "+f"(c[3])
        : "r"(a0), "r"(a1), "r"(a2), "r"(a3), "r"(b0), "r"(b1));
}

// ---------------------------------------------------------------------------
// Kernel 1: per (qt, bh) strip of 128 x 1024.
// e = exp(QK^T/8 masked + bias) stored to score buffer (raw exp!), plus
// g_inv_l = 1 / row-sum(e).  3xTF32 split MMA.
// Smem: QF = Q fragments raw fp32 (float4 per (wq,kk,mt,lane));
//       KF = K fragments as uint4 {bhi0,bhi1,blo0,blo1} per (wk,kk,nt,lane).
// ---------------------------------------------------------------------------
__global__ __launch_bounds__(256, 2)
void qks_kernel(const float* __restrict__ Q, const float* __restrict__ K,
                const int* __restrict__ mask, const float* __restrict__ bias,
                float* __restrict__ score)
{
    extern __shared__ float sm[];
    float*    QF   = sm;                          // 8192 floats (32 KB)
    uint32_t* KF   = (uint32_t*)(sm + 8192);      // 16384 uints (64 KB)
    float*    sred = sm + 8192 + 16384;           // 256 floats

    const int tid  = threadIdx.x;
    const int lane = tid & 31, wid = tid >> 5;
    const int wq = wid & 3, wk = wid >> 2;
    const int g = lane >> 2, t = lane & 3;
    const int qt = blockIdx.x, bh = blockIdx.y;
    const int b = bh >> 4, h = bh & 15;

    // ---- load Q tile once, scatter into fragment-major layout ----
    {
        const float4* Qg = (const float4*)(Q + ((size_t)bh * L + qt * 128) * D);
        const int row = tid >> 1;
        const int wqr = row >> 5, m32 = row & 31, mt = m32 >> 4, gp = m32 & 15;
        const int gg = gp & 7, rlo = gp >> 3;
        #pragma unroll
        for (int it = 0; it < 8; it++) {
            int qcol = (tid & 1) + it * 2;
            float4 v = Qg[row * 16 + qcol];
            int kk = qcol >> 1, r = ((qcol & 1) << 1) | rlo;
            float* dst = QF + ((wqr * 8 + kk) * 2 + mt) * 128 + r;
            dst[(gg * 4 + 0) * 4] = v.x;
            dst[(gg * 4 + 1) * 4] = v.y;
            dst[(gg * 4 + 2) * 4] = v.z;
            dst[(gg * 4 + 3) * 4] = v.w;
        }
    }

    float l_run[4] = {0.f, 0.f, 0.f, 0.f};

    for (int kt = 0; kt < 8; kt++) {
        __syncthreads();
        // ---- load K tile, split hi/lo tf32, fragment-major ----
        {
            const float4* Kg = (const float4*)(K + ((size_t)bh * L + kt * 128) * D);
            const int krow = tid >> 1;
            const int wkr = krow >> 6, n64 = krow & 63, nt = n64 >> 3, gg = n64 & 7;
            #pragma unroll
            for (int it = 0; it < 8; it++) {
                int qcol = (tid & 1) + it * 2;
                float4 v = Kg[krow * 16 + qcol];
                int kk = qcol >> 1, word = qcol & 1;
                uint32_t* dst = KF + ((wkr * 8 + kk) * 8 + nt) * 128 + word;
                #pragma unroll
                for (int j = 0; j < 4; j++) {
                    float x = (&v.x)[j];
                    uint32_t hi = f2tf(x);
                    uint32_t lo = f2tf(x - __uint_as_float(hi));
                    dst[(gg * 4 + j) * 4]     = hi;
                    dst[(gg * 4 + j) * 4 + 2] = lo;
                }
            }
        }
        __syncthreads();

        float acc[2][8][4];
        #pragma unroll
        for (int mt = 0; mt < 2; mt++)
            #pragma unroll
            for (int nt = 0; nt < 8; nt++)
                #pragma unroll
                for (int r = 0; r < 4; r++) acc[mt][nt][r] = 0.f;

        const float4* QF4 = (const float4*)QF;
        const uint4*  KF4 = (const uint4*)KF;

        #pragma unroll
        for (int kk = 0; kk < 8; kk++) {
            uint32_t ahi[2][4], alo[2][4];
            #pragma unroll
            for (int mt = 0; mt < 2; mt++) {
                float4 a = QF4[((wq * 8 + kk) * 2 + mt) * 32 + lane];
                #pragma unroll
                for (int j = 0; j < 4; j++) {
                    float x = (&a.x)[j];
                    uint32_t hi = f2tf(x);
                    ahi[mt][j] = hi;
                    alo[mt][j] = f2tf(x - __uint_as_float(hi));
                }
            }
            #pragma unroll
            for (int nt = 0; nt < 8; nt++) {
                uint4 bb = KF4[((wk * 8 + kk) * 8 + nt) * 32 + lane];
                #pragma unroll
                for (int mt = 0; mt < 2; mt++) {
                    mma_tf32(acc[mt][nt], ahi[mt][0], ahi[mt][1], ahi[mt][2], ahi[mt][3], bb.z, bb.w);
                    mma_tf32(acc[mt][nt], alo[mt][0], alo[mt][1], alo[mt][2], alo[mt][3], bb.x, bb.y);
                    mma_tf32(acc[mt][nt], ahi[mt][0], ahi[mt][1], ahi[mt][2], ahi[mt][3], bb.x, bb.y);
                }
            }
        }

        // ---- epilogue: scale, mask, bias, store e=exp(s), accumulate l ----
        const int q0 = qt * 128 + wq * 32;
        const int cp0 = kt * 64 + wk * 32;   // float2 col-index base for this warp
        #pragma unroll
        for (int mt = 0; mt < 2; mt++)
            #pragma unroll
            for (int half = 0; half < 2; half++) {
                int row = q0 + mt * 16 + half * 8 + g;
                const int2*   mrow = (const int2*)  (mask  + ((size_t)b  * L + row) * L);
                const float2* brow = (const float2*)(bias  + ((size_t)h  * L + row) * L);
                float2*       srow = (float2*)      (score + ((size_t)bh * L + row) * L);
                float lsum = 0.f;
                #pragma unroll
                for (int nt = 0; nt < 8; nt++) {
                    int cp = cp0 + nt * 4 + t;
                    int2   mv = mrow[cp];
                    float2 bv = brow[cp];
                    float s0 = acc[mt][nt][half * 2 + 0] * 0.125f;
                    float s1 = acc[mt][nt][half * 2 + 1] * 0.125f;
                    s0 = (mv.x == 0 ? -10000.f : s0) + bv.x;
                    s1 = (mv.y == 0 ? -10000.f : s1) + bv.y;
                    float e0 = __expf(s0), e1 = __expf(s1);
                    srow[cp] = make_float2(e0, e1);
                    lsum += e0 + e1;
                }
                l_run[mt * 2 + half] += lsum;
            }
    }

    // reduce l over the 4 t-lanes, then across the 2 wk groups
    #pragma unroll
    for (int li = 0; li < 4; li++) {
        l_run[li] += __shfl_xor_sync(0xffffffffu, l_run[li], 1);
        l_run[li] += __shfl_xor_sync(0xffffffffu, l_run[li], 2);
    }
    __syncthreads();
    if (t == 0) {
        #pragma unroll
        for (int li = 0; li < 4; li++) {
            int row = wq * 32 + (li >> 1) * 16 + (li & 1) * 8 + g;
            sred[wk * 128 + row] = l_run[li];
        }
    }
    __syncthreads();
    if (tid < 128) {
        float l = sred[tid] + sred[128 + tid];
        g_inv_l[(size_t)bh * L + qt * 128 + tid] = 1.0f / l;
    }
}

// ---------------------------------------------------------------------------
// Kernel 2: O = P V with P = e * inv_l; writes normalized p over e in score.
// Fragment-major pre-converted tf32 smem; register-staged software pipeline.
// 8 warps x 16 rows; k-chunks of 64.
// ---------------------------------------------------------------------------
struct Stage { float4 se[8]; float4 sv[4]; };

__device__ __forceinline__ void load_stage(Stage& st, const float* sbase,
                                           const float4* Vg, int c, int tid)
{
    const int prow = tid >> 1;
    #pragma unroll
    for (int it = 0; it < 8; it++) {
        int qcol = (tid & 1) + it * 2;
        st.se[it] = *(const float4*)(sbase + (size_t)prow * L + c * 64 + qcol * 4);
    }
    const int vrow = tid >> 2;
    #pragma unroll
    for (int it = 0; it < 4; it++) {
        int qd = (tid & 3) + it * 4;
        st.sv[it] = Vg[(size_t)(c * 64 + vrow) * 16 + qd];
    }
}

__global__ __launch_bounds__(256, 2)
void pv_kernel(const float* __restrict__ V, float* score, float* __restrict__ out)
{
    extern __shared__ uint32_t smu[];
    uint32_t* AF   = smu;                    // 8192 uints (32 KB): P fragments tf32
    uint32_t* VF   = smu + 8192;             // 4096 uints (16 KB): V fragments tf32
    float*    sinv = (float*)(smu + 8192 + 4096);   // 128 floats

    const int tid  = threadIdx.x;
    const int lane = tid & 31, wid = tid >> 5;
    const int g = lane >> 2, t = lane & 3;
    const int qt = blockIdx.x, bh = blockIdx.y;

    const float4* Vg    = (const float4*)(V + (size_t)bh * L * D);
    float*        sbase = score + ((size_t)bh * L + qt * 128) * L;

    Stage st;
    load_stage(st, sbase, Vg, 0, tid);
    if (tid < 128) sinv[tid] = g_inv_l[(size_t)bh * L + qt * 128 + tid];
    __syncthreads();
    const float il = sinv[tid >> 1];

    float acc[8][4];
    #pragma unroll
    for (int nt = 0; nt < 8; nt++)
        #pragma unroll
        for (int r = 0; r < 4; r++) acc[nt][r] = 0.f;

    // per-thread constant scatter indices
    const int prow = tid >> 1;
    const int wqr = prow >> 4, gp = prow & 15, gg = gp & 7, rlo = gp >> 3;
    const int vrow = tid >> 2;
    const int vkk = vrow >> 3, ts = vrow & 7, vword = ts >> 2, vt = ts & 3;

    for (int c = 0; c < 16; c++) {
        __syncthreads();   // previous MMA done reading smem
        // ---- transform + store stage: p = e*il -> gmem + fragment smem ----
        #pragma unroll
        for (int it = 0; it < 8; it++) {
            int qcol = (tid & 1) + it * 2;
            float4 p;
            p.x = st.se[it].x * il; p.y = st.se[it].y * il;
            p.z = st.se[it].z * il; p.w = st.se[it].w * il;
            *(float4*)(sbase + (size_t)prow * L + c * 64 + qcol * 4) = p;
            int kk = qcol >> 1, r = ((qcol & 1) << 1) | rlo;
            uint32_t* dst = AF + (wqr * 8 + kk) * 128 + r;
            dst[(gg * 4 + 0) * 4] = f2tf(p.x);
            dst[(gg * 4 + 1) * 4] = f2tf(p.y);
            dst[(gg * 4 + 2) * 4] = f2tf(p.z);
            dst[(gg * 4 + 3) * 4] = f2tf(p.w);
        }
        #pragma unroll
        for (int it = 0; it < 4; it++) {
            int qd = (tid & 3) + it * 4;
            #pragma unroll
            for (int j = 0; j < 4; j++) {
                int n = qd * 4 + j;
                int nt = n >> 3, gn = n & 7;
                VF[((vkk * 8 + nt) * 32 + gn * 4 + vt) * 2 + vword] = f2tf((&st.sv[it].x)[j]);
            }
        }
        __syncthreads();

        if (c < 15) load_stage(st, sbase, Vg, c + 1, tid);   // overlap with MMA

        const uint4* AF4 = (const uint4*)AF;
        const uint2* VF2 = (const uint2*)VF;
        #pragma unroll
        for (int kk = 0; kk < 8; kk++) {
            uint4 a = AF4[(wid * 8 + kk) * 32 + lane];
            #pragma unroll
            for (int nt = 0; nt < 8; nt++) {
                uint2 bb = VF2[(kk * 8 + nt) * 32 + lane];
                mma_tf32(acc[nt], a.x, a.y, a.z, a.w, bb.x, bb.y);
            }
        }
    }

    #pragma unroll
    for (int half = 0; half < 2; half++) {
        int row = qt * 128 + wid * 16 + half * 8 + g;
        float2* orow = (float2*)(out + ((size_t)bh * L + row) * D);
        #pragma unroll
        for (int nt = 0; nt < 8; nt++)
            orow[nt * 4 + t] = make_float2(acc[nt][half * 2], acc[nt][half * 2 + 1]);
    }
}

// ---------------------------------------------------------------------------
extern "C" void kernel_launch(void* const* d_in, const int* in_sizes, int n_in,
                              void* d_out, int out_size)
{
    const float* Q    = (const float*)d_in[0];
    const float* K    = (const float*)d_in[1];
    const float* V    = (const float*)d_in[2];
    const int*   mask = (const int*)  d_in[3];
    const float* bias = (const float*)d_in[4];

    float* out   = (float*)d_out;
    float* score = out + OUT_ELEMS;   // tuple order: (out, score)

    const int qk_smem = (8192 + 16384 + 256) * 4;    // 99328 B
    const int pv_smem = (8192 + 4096 + 128) * 4;     // 49664 B
    cudaFuncSetAttribute(qks_kernel, cudaFuncAttributeMaxDynamicSharedMemorySize, qk_smem);
    cudaFuncSetAttribute(pv_kernel,  cudaFuncAttributeMaxDynamicSharedMemorySize, pv_smem);

    qks_kernel<<<dim3(8, 64), 256, qk_smem>>>(Q, K, mask, bias, score);
    pv_kernel <<<dim3(8, 64), 256, pv_smem>>>(V, score, out);
}